// round 12
// baseline (speedup 1.0000x reference)
#include <cuda_runtime.h>
#include <cuda_bf16.h>
#include <cstdint>
#include <math.h>

typedef unsigned int       u32;
typedef unsigned long long u64;

// ---------------------------------------------------------------------------
// Scratch (static device globals - no allocations anywhere)
// ---------------------------------------------------------------------------
#define MAXACT (8*64*128*128)
__device__ float  g_bufA[MAXACT];
__device__ float  g_bufB[MAXACT];
__device__ float  g_part[4194304];
__device__ int4   g_tIdx[196416];
__device__ float4 g_tW  [196416];
__device__ float  g_vec[8*512];
__device__ float  g_fc1o[8*4096];
__device__ float  g_fc2o[8*4096];
__device__ __nv_bfloat16 g_Shi[75497472];
__device__ __nv_bfloat16 g_Slo[75497472];
__device__ __nv_bfloat16 g_Whi[14712832];
__device__ __nv_bfloat16 g_Wlo[14712832];

// ---------------------------------------------------------------------------
// Helpers
// ---------------------------------------------------------------------------
__device__ __forceinline__ void cp_async16(u32 dst, const void* src) {
    asm volatile("cp.async.cg.shared.global [%0], [%1], 16;" :: "r"(dst), "l"(src) : "memory");
}

__device__ __forceinline__ u32 smem_u32(const void* p) {
    u32 a;
    asm("{ .reg .u64 t; cvta.to.shared.u64 t, %1; cvt.u32.u64 %0, t; }" : "=r"(a) : "l"(p));
    return a;
}

__device__ __forceinline__ void mma16816(float* c, const u32* a, const u32* b) {
    asm volatile(
        "mma.sync.aligned.m16n8k16.row.col.f32.bf16.bf16.f32 "
        "{%0,%1,%2,%3}, {%4,%5,%6,%7}, {%8,%9}, {%0,%1,%2,%3};"
        : "+f"(c[0]), "+f"(c[1]), "+f"(c[2]), "+f"(c[3])
        : "r"(a[0]), "r"(a[1]), "r"(a[2]), "r"(a[3]), "r"(b[0]), "r"(b[1]));
}

__device__ __forceinline__ void ldm_x4(u32* r, u32 addr) {
    asm volatile("ldmatrix.sync.aligned.m8n8.x4.shared.b16 {%0,%1,%2,%3}, [%4];"
        : "=r"(r[0]), "=r"(r[1]), "=r"(r[2]), "=r"(r[3]) : "r"(addr));
}

__device__ __forceinline__ float* sel_buf(int s) {
    if (s == 1) return g_bufA;
    if (s == 2) return g_bufB;
    return g_part;
}

// ---------------------------------------------------------------------------
// Sampling tables for all 5 resolutions in ONE launch (86 blocks)
// ---------------------------------------------------------------------------
__global__ void make_table_all()
{
    int bi = blockIdx.x;
    int r, pb;
    if (bi < 64)      { r = 0; pb = bi; }
    else if (bi < 80) { r = 1; pb = bi - 64; }
    else if (bi < 84) { r = 2; pb = bi - 80; }
    else if (bi < 85) { r = 3; pb = bi - 84; }
    else              { r = 4; pb = bi - 85; }
    const int Hs[5]    = {128, 64, 32, 16, 8};
    const int bases[5] = {0, 147456, 184320, 193536, 195840};
    int H = Hs[r];
    int base = bases[r];
    int p = pb * blockDim.x + threadIdx.x;
    int HW = H * H;
    if (p >= HW) return;

    int y = p / H, x = p % H;
    float c = H * 0.5f - 0.5f;
    const float TWO_PI = 6.283185307179586f;
    const float PI4    = 0.7853981633974483f;
    float t = atan2f((float)x - c, (float)y - c);
    if (t < 0.f) t += TWO_PI;
    t = rintf(t * 10000.f) / 10000.f;

    #pragma unroll
    for (int k = 0; k < 9; k++) {
        float offy, offx;
        if (k == 4) { offy = 0.f; offx = 0.f; }
        else {
            int m = (k < 4) ? k : (k - 1);
            float ay = (float)(1 - k / 3);
            float ax = (float)(1 - k % 3);
            float ang = t + PI4 * (float)m;
            offy = cosf(ang) + ay;
            offx = sinf(ang) + ax;
        }
        float py = (float)(y - 1 + k / 3) + offy;
        float px = (float)(x - 1 + k % 3) + offx;
        float y0f = floorf(py), x0f = floorf(px);
        float wy = py - y0f, wx = px - x0f;
        int y0 = (int)y0f, x0 = (int)x0f;

        int4 ii; float4 ww;
        {
            int yy = y0, xx = x0;
            bool v = (yy >= 0 && yy <= H-1 && xx >= 0 && xx <= H-1);
            int yc = min(max(yy,0),H-1), xc = min(max(xx,0),H-1);
            ii.x = yc*H + xc; ww.x = v ? (1.f-wy)*(1.f-wx) : 0.f;
        }
        {
            int yy = y0, xx = x0+1;
            bool v = (yy >= 0 && yy <= H-1 && xx >= 0 && xx <= H-1);
            int yc = min(max(yy,0),H-1), xc = min(max(xx,0),H-1);
            ii.y = yc*H + xc; ww.y = v ? (1.f-wy)*wx : 0.f;
        }
        {
            int yy = y0+1, xx = x0;
            bool v = (yy >= 0 && yy <= H-1 && xx >= 0 && xx <= H-1);
            int yc = min(max(yy,0),H-1), xc = min(max(xx,0),H-1);
            ii.z = yc*H + xc; ww.z = v ? wy*(1.f-wx) : 0.f;
        }
        {
            int yy = y0+1, xx = x0+1;
            bool v = (yy >= 0 && yy <= H-1 && xx >= 0 && xx <= H-1);
            int yc = min(max(yy,0),H-1), xc = min(max(xx,0),H-1);
            ii.w = yc*H + xc; ww.w = v ? wy*wx : 0.f;
        }
        g_tIdx[base + k*HW + p] = ii;
        g_tW  [base + k*HW + p] = ww;
    }
}

// ---------------------------------------------------------------------------
// All 13 weight preps in ONE launch. Block ranges scanned from const config.
// ---------------------------------------------------------------------------
__global__ void wprep_all(const float* w0, const float* w1, const float* w2,
                          const float* w3, const float* w4, const float* w5,
                          const float* w6, const float* w7, const float* w8,
                          const float* w9, const float* w10, const float* w11,
                          const float* w12)
{
    const float* ws[13] = {w0,w1,w2,w3,w4,w5,w6,w7,w8,w9,w10,w11,w12};
    const int lC[13] = {3,64,64,128,128,256,256,256,512,512,512,512,512};
    const int lO[13] = {64,64,128,128,256,256,256,512,512,512,512,512,512};
    const int kp[13] = {64,576,576,1152,1152,2304,2304,2304,4608,4608,4608,4608,4608};

    int bi = blockIdx.x;
    int li = 0, cum = 0;
    for (li = 0; li < 13; li++) {
        int nb = (lO[li]*kp[li] + 255) >> 8;
        if (bi < cum + nb) break;
        cum += nb;
    }
    if (li >= 13) return;
    int tot = lO[li] * kp[li];
    int i = (bi - cum) * 256 + threadIdx.x;
    if (i >= tot) return;
    int woff = 0;
    for (int j = 0; j < li; j++) woff += lO[j]*kp[j];
    int CK = lC[li] * 9;
    int Kpad = kp[li];
    int o = i / Kpad;
    int kk = i - o * Kpad;
    float v = 0.f;
    if (kk < CK) v = ws[li][(size_t)o * CK + kk];
    __nv_bfloat16 h = __float2bfloat16(v);
    g_Whi[woff + i] = h;
    g_Wlo[woff + i] = __float2bfloat16(v - __bfloat162float(h));
}

// ---------------------------------------------------------------------------
// Sampler: bilinear im2col -> g_Shi/g_Slo [N][Kpad] bf16
// ---------------------------------------------------------------------------
__global__ void sample_kernel(const float* __restrict__ xext, int srcSel,
                              int tbase, int C, int HW, int Kpad, int total)
{
    int i = blockIdx.x * blockDim.x + threadIdx.x;
    if (i >= total) return;
    const float* x = xext;
    if (srcSel == 1) x = g_bufA;
    if (srcSel == 2) x = g_bufB;
    int c = i % C, n = i / C;
    int b = n / HW, p = n - b * HW;
    const float* xc = x + ((size_t)b * C + c) * HW;
    size_t ro = (size_t)n * Kpad + c * 9;
    #pragma unroll
    for (int k = 0; k < 9; k++) {
        int4   ii = __ldg(&g_tIdx[tbase + k*HW + p]);
        float4 ww = __ldg(&g_tW  [tbase + k*HW + p]);
        float s = ww.x*__ldg(xc+ii.x) + ww.y*__ldg(xc+ii.y)
                + ww.z*__ldg(xc+ii.z) + ww.w*__ldg(xc+ii.w);
        __nv_bfloat16 h = __float2bfloat16(s);
        g_Shi[ro + k] = h;
        g_Slo[ro + k] = __float2bfloat16(s - __bfloat162float(h));
    }
    if (c == C - 1) {
        __nv_bfloat16 z = __float2bfloat16(0.f);
        for (int kk = C*9; kk < Kpad; kk++) {
            g_Shi[(size_t)n*Kpad + kk] = z;
            g_Slo[(size_t)n*Kpad + kk] = z;
        }
    }
}

// ---------------------------------------------------------------------------
// mma.sync GEMM, NT=64 fixed. CTA tile 128 pixels x 64 outputs, 256 threads
// (8 warps, warp tile 32x32), k-chunk 32, 2-stage cp.async, ldmatrix frags,
// 2 CTAs/SM. Smem rows pitch 80 B -> conflict-free ldmatrix phases.
// Stage layout: [Ahi 10240 | Alo 10240 | Bhi 5120 | Blo 5120] = 30720 B.
// ---------------------------------------------------------------------------
__global__ void __launch_bounds__(256, 2)
gemm_kernel(int woff, int outSel, int O, int Npix, int Kpad, int kSplit, int HW)
{
    extern __shared__ char sm[];
    const int tid  = threadIdx.x;
    const int wid  = tid >> 5;
    const int lane = tid & 31;
    const int g    = lane >> 2;
    const int t    = lane & 3;
    const int n0 = blockIdx.x * 128;
    const int o0 = blockIdx.y * 64;
    const int kc = blockIdx.z;
    const int nCh = (Kpad / kSplit) >> 5;
    const int ci0 = kc * nCh;

    const int warpM = (wid & 3) * 32;
    const int warpN = (wid >> 2) * 32;

    const u32 sb = smem_u32(sm);

    // ldmatrix per-lane offsets
    const int aRow = ((lane >> 3) & 1) * 8 + (lane & 7);
    const int aK   = (lane >> 4) * 8;
    const int bN   = (lane >> 4) * 8 + (lane & 7);
    const int bK   = ((lane >> 3) & 1) * 8;

    float acc[2][4][4];
    #pragma unroll
    for (int mt = 0; mt < 2; mt++)
        #pragma unroll
        for (int nt = 0; nt < 4; nt++)
            #pragma unroll
            for (int r = 0; r < 4; r++) acc[mt][nt][r] = 0.f;

    const int nGran = 1536;   // Ahi 512 + Alo 512 + Bhi 256 + Blo 256

    for (int i = 0; i < nCh; i++) {
        int s = i & 1;
        if (i + 1 < nCh) {
            int colOff = (ci0 + i + 1) * 32;
            u32 stBase = sb + (u32)((1 - s) * 30720);
            for (int gr = tid; gr < nGran; gr += 256) {
                if (gr < 512) {
                    int row = gr >> 2, gi = gr & 3;
                    cp_async16(stBase + (u32)(row*80 + gi*16),
                               g_Shi + (size_t)(n0+row)*Kpad + colOff + gi*8);
                } else if (gr < 1024) {
                    int gg = gr - 512;
                    int row = gg >> 2, gi = gg & 3;
                    cp_async16(stBase + (u32)(10240 + row*80 + gi*16),
                               g_Slo + (size_t)(n0+row)*Kpad + colOff + gi*8);
                } else if (gr < 1280) {
                    int gg = gr - 1024;
                    int row = gg >> 2, gi = gg & 3;
                    cp_async16(stBase + (u32)(20480 + row*80 + gi*16),
                               g_Whi + woff + (size_t)(o0+row)*Kpad + colOff + gi*8);
                } else {
                    int gg = gr - 1280;
                    int row = gg >> 2, gi = gg & 3;
                    cp_async16(stBase + (u32)(25600 + row*80 + gi*16),
                               g_Wlo + woff + (size_t)(o0+row)*Kpad + colOff + gi*8);
                }
            }
            asm volatile("cp.async.commit_group;" ::: "memory");
            asm volatile("cp.async.wait_group 1;" ::: "memory");
        } else {
            asm volatile("cp.async.wait_group 0;" ::: "memory");
        }
        if (i == 0) {
            int colOff = ci0 * 32;
            u32 stBase = sb;
            for (int gr = tid; gr < nGran; gr += 256) {
                if (gr < 512) {
                    int row = gr >> 2, gi = gr & 3;
                    cp_async16(stBase + (u32)(row*80 + gi*16),
                               g_Shi + (size_t)(n0+row)*Kpad + colOff + gi*8);
                } else if (gr < 1024) {
                    int gg = gr - 512;
                    int row = gg >> 2, gi = gg & 3;
                    cp_async16(stBase + (u32)(10240 + row*80 + gi*16),
                               g_Slo + (size_t)(n0+row)*Kpad + colOff + gi*8);
                } else if (gr < 1280) {
                    int gg = gr - 1024;
                    int row = gg >> 2, gi = gg & 3;
                    cp_async16(stBase + (u32)(20480 + row*80 + gi*16),
                               g_Whi + woff + (size_t)(o0+row)*Kpad + colOff + gi*8);
                } else {
                    int gg = gr - 1280;
                    int row = gg >> 2, gi = gg & 3;
                    cp_async16(stBase + (u32)(25600 + row*80 + gi*16),
                               g_Wlo + woff + (size_t)(o0+row)*Kpad + colOff + gi*8);
                }
            }
            asm volatile("cp.async.commit_group;" ::: "memory");
            asm volatile("cp.async.wait_group 0;" ::: "memory");
        }
        __syncthreads();

        // ---- compute chunk from stage s via ldmatrix fragments ----
        u32 stA_h = sb + (u32)(s * 30720);
        u32 stA_l = stA_h + 10240u;
        u32 stB_h = stA_h + 20480u;
        u32 stB_l = stA_h + 25600u;

        #pragma unroll
        for (int k0 = 0; k0 < 32; k0 += 16) {
            u32 ah[2][4], al[2][4], bh2[2][4], bl2[2][4];
            #pragma unroll
            for (int mt = 0; mt < 2; mt++) {
                u32 off = (u32)((warpM + mt*16 + aRow)*80 + (k0 + aK)*2);
                ldm_x4(ah[mt], stA_h + off);
                ldm_x4(al[mt], stA_l + off);
            }
            #pragma unroll
            for (int pr = 0; pr < 2; pr++) {
                u32 off = (u32)((warpN + pr*16 + bN)*80 + (k0 + bK)*2);
                ldm_x4(bh2[pr], stB_h + off);
                ldm_x4(bl2[pr], stB_l + off);
            }
            #pragma unroll
            for (int mt = 0; mt < 2; mt++) {
                #pragma unroll
                for (int nt = 0; nt < 4; nt++) {
                    const u32* bh_ = &bh2[nt >> 1][(nt & 1) * 2];
                    const u32* bl_ = &bl2[nt >> 1][(nt & 1) * 2];
                    mma16816(acc[mt][nt], ah[mt], bh_);
                    mma16816(acc[mt][nt], ah[mt], bl_);
                    mma16816(acc[mt][nt], al[mt], bh_);
                }
            }
        }
        __syncthreads();
    }

    // ---- epilogue: direct register stores (+relu / split-K slice) ----
    float* ob = sel_buf(outSel);
    int doRelu = 1;
    if (outSel == 3) {
        ob = g_part + (size_t)kc * (size_t)O * (size_t)Npix;
        doRelu = 0;
    }
    #pragma unroll
    for (int mt = 0; mt < 2; mt++) {
        #pragma unroll
        for (int nt = 0; nt < 4; nt++) {
            int pr0 = n0 + warpM + mt*16 + g;
            int pr1 = pr0 + 8;
            int oc  = o0 + warpN + nt*8 + 2*t;
            int b0 = pr0 / HW, p0 = pr0 - b0 * HW;
            int b1 = pr1 / HW, p1 = pr1 - b1 * HW;
            float v0 = acc[mt][nt][0];
            float v1 = acc[mt][nt][1];
            float v2 = acc[mt][nt][2];
            float v3 = acc[mt][nt][3];
            if (doRelu) {
                v0 = fmaxf(v0, 0.f); v1 = fmaxf(v1, 0.f);
                v2 = fmaxf(v2, 0.f); v3 = fmaxf(v3, 0.f);
            }
            ob[((size_t)b0 * O + oc)     * (size_t)HW + p0] = v0;
            ob[((size_t)b0 * O + oc + 1) * (size_t)HW + p0] = v1;
            ob[((size_t)b1 * O + oc)     * (size_t)HW + p1] = v2;
            ob[((size_t)b1 * O + oc + 1) * (size_t)HW + p1] = v3;
        }
    }
}

// ---------------------------------------------------------------------------
// Split-K reduce + ReLU (deterministic)
// ---------------------------------------------------------------------------
__global__ void reduce_relu_kernel(int outSel, int n, int kSplit)
{
    int i = blockIdx.x * blockDim.x + threadIdx.x;
    if (i >= n) return;
    float s = 0.f;
    for (int j = 0; j < kSplit; j++) s += g_part[(size_t)j*n + i];
    float* out = sel_buf(outSel);
    out[i] = fmaxf(s, 0.f);
}

// ---------------------------------------------------------------------------
// 2x2 max pool: inSel -> outSel
// ---------------------------------------------------------------------------
__global__ void pool_kernel(int inSel, int outSel, int C, int H)
{
    const float* in = sel_buf(inSel);
    float* out = sel_buf(outSel);
    int Ho = H / 2;
    int total = 8 * C * Ho * Ho;
    int i = blockIdx.x * blockDim.x + threadIdx.x;
    if (i >= total) return;
    int xo = i % Ho; int t = i / Ho;
    int yo = t % Ho; t /= Ho;
    int cc = t % C;  int b = t / C;
    const float* base = in + (((size_t)b*C + cc)*H + yo*2)*H + xo*2;
    out[i] = fmaxf(fmaxf(base[0], base[1]), fmaxf(base[H], base[H+1]));
}

// (8,512,4,4) in g_bufB -> (8,512) mean in g_vec
__global__ void avg_kernel()
{
    int i = blockIdx.x * blockDim.x + threadIdx.x;
    if (i >= 8*512) return;
    const float* p = g_bufB + (size_t)i * 16;
    float s = 0.f;
    #pragma unroll
    for (int j = 0; j < 16; j++) s += p[j];
    g_vec[i] = s * (1.f/16.f);
}

// ---------------------------------------------------------------------------
// FC layers
// ---------------------------------------------------------------------------
__global__ void fc_kernel(const float* __restrict__ W, const float* __restrict__ bias,
                          float* dout, int stage, int K, int O)
{
    const float* x = g_vec;
    if (stage == 1) x = g_fc1o;
    if (stage == 2) x = g_fc2o;
    float* y = g_fc1o;
    if (stage == 1) y = g_fc2o;
    if (stage == 2) y = dout;
    int relu = (stage < 2) ? 1 : 0;

    int o = blockIdx.x;
    float acc[8];
    #pragma unroll
    for (int i = 0; i < 8; i++) acc[i] = 0.f;
    const float* wr = W + (size_t)o * K;
    for (int k = threadIdx.x; k < K; k += 128) {
        float wv = wr[k];
        #pragma unroll
        for (int b = 0; b < 8; b++) acc[b] = fmaf(x[(size_t)b*K + k], wv, acc[b]);
    }
    __shared__ float red[8][128];
    #pragma unroll
    for (int b = 0; b < 8; b++) red[b][threadIdx.x] = acc[b];
    __syncthreads();
    for (int s = 64; s > 0; s >>= 1) {
        if (threadIdx.x < s) {
            #pragma unroll
            for (int b = 0; b < 8; b++)
                red[b][threadIdx.x] += red[b][threadIdx.x + s];
        }
        __syncthreads();
    }
    if (threadIdx.x < 8) {
        int b = threadIdx.x;
        float v = red[b][0] + bias[o];
        if (relu) v = fmaxf(v, 0.f);
        y[(size_t)b*O + o] = v;
    }
}

// ---------------------------------------------------------------------------
// Host orchestration
// ---------------------------------------------------------------------------
extern "C" void kernel_launch(void* const* d_in, const int* in_sizes, int n_in,
                              void* d_out, int out_size)
{
    const float* x = (const float*)d_in[0];
    const float* w[13];
    for (int i = 0; i < 13; i++) w[i] = (const float*)d_in[1+i];
    const float* fc1w = (const float*)d_in[14];
    const float* fc1b = (const float*)d_in[15];
    const float* fc2w = (const float*)d_in[16];
    const float* fc2b = (const float*)d_in[17];
    const float* fc3w = (const float*)d_in[18];
    const float* fc3b = (const float*)d_in[19];

    cudaFuncSetAttribute(gemm_kernel,
                         cudaFuncAttributeMaxDynamicSharedMemorySize, 61440);

    // launch 0: all sampling tables
    make_table_all<<<86, 256>>>();

    // launch 1: all weight preps
    const int lC[13] = {3,64,64,128,128,256,256,256,512,512,512,512,512};
    const int lO[13] = {64,64,128,128,256,256,256,512,512,512,512,512,512};
    int kpad[13];
    int woff[13];
    int wacc = 0;
    int nblk = 0;
    for (int i = 0; i < 13; i++) {
        kpad[i] = ((lC[i]*9 + 63) / 64) * 64;
        woff[i] = wacc;
        wacc += lO[i] * kpad[i];
        nblk += (lO[i]*kpad[i] + 255) / 256;
    }
    wprep_all<<<nblk, 256>>>(w[0],w[1],w[2],w[3],w[4],w[5],w[6],
                             w[7],w[8],w[9],w[10],w[11],w[12]);

    // per-layer schedule
    const int tbase[5] = {0, 147456, 184320, 193536, 195840};
    const int lH[13]   = {128,128,64,64,32,32,32,16,16,16,8,8,8};
    const int lKS[13]  = {1,1,1,1,1,1,1,2,2,2,8,8,8};
    const int srcSel[13] = {0,1,1,2,2,1,2,2,1,2,2,1,2};
    const int dstSel[13] = {1,2,2,1,1,2,1,1,2,1,1,2,1};

    for (int li = 0; li < 13; li++) {
        int C = lC[li], O = lO[li], H = lH[li], kSplit = lKS[li];
        int HW = H * H;
        int Kpad = kpad[li];
        int ti = 4;
        if (HW == 16384) ti = 0;
        else if (HW == 4096) ti = 1;
        else if (HW == 1024) ti = 2;
        else if (HW == 256) ti = 3;

        int total = 8 * HW * C;
        sample_kernel<<<(total + 255)/256, 256>>>(x, srcSel[li], tbase[ti],
                                                  C, HW, Kpad, total);

        int Npix = 8 * HW;
        dim3 grid(Npix/128, O/64, kSplit);
        int outSel = dstSel[li];
        if (kSplit > 1) outSel = 3;
        gemm_kernel<<<grid, 256, 61440>>>(woff[li], outSel, O, Npix, Kpad, kSplit, HW);
        if (kSplit > 1) {
            int n = O * Npix;
            reduce_relu_kernel<<<(n + 255)/256, 256>>>(dstSel[li], n, kSplit);
        }

        if (li == 1)  pool_kernel<<<(8*64*64*64  + 255)/256, 256>>>(2, 1, 64, 128);
        if (li == 3)  pool_kernel<<<(8*128*32*32 + 255)/256, 256>>>(1, 2, 128, 64);
        if (li == 6)  pool_kernel<<<(8*256*16*16 + 255)/256, 256>>>(1, 2, 256, 32);
        if (li == 9)  pool_kernel<<<(8*512*8*8   + 255)/256, 256>>>(1, 2, 512, 16);
        if (li == 12) pool_kernel<<<(8*512*4*4   + 255)/256, 256>>>(1, 2, 512, 8);
    }

    avg_kernel<<<(8*512 + 255)/256, 256>>>();

    fc_kernel<<<4096, 128>>>(fc1w, fc1b, (float*)d_out, 0, 512, 4096);
    fc_kernel<<<4096, 128>>>(fc2w, fc2b, (float*)d_out, 1, 4096, 4096);
    fc_kernel<<<30,   128>>>(fc3w, fc3b, (float*)d_out, 2, 4096, 30);
}

// round 14
// speedup vs baseline: 2.7266x; 2.7266x over previous
#include <cuda_runtime.h>
#include <cuda_bf16.h>
#include <cstdint>
#include <math.h>

typedef unsigned int       u32;
typedef unsigned long long u64;

// ---------------------------------------------------------------------------
// Scratch (static device globals - no allocations anywhere)
// All activations are NHWC: [b][p][c], c contiguous.
// ---------------------------------------------------------------------------
#define MAXACT (8*64*128*128)
__device__ float  g_bufA[MAXACT];
__device__ float  g_bufB[MAXACT];
__device__ float  g_part[4194304];
__device__ int4   g_tIdx[196416];
__device__ float4 g_tW  [196416];
__device__ float  g_vec[8*512];
__device__ float  g_fc1o[8*4096];
__device__ float  g_fc2o[8*4096];
// K-dim order is tap-major: kk = tap*C + c  (S and W agree)
__device__ __nv_bfloat16 g_Shi[75497472];
__device__ __nv_bfloat16 g_Slo[75497472];
__device__ __nv_bfloat16 g_Whi[14712832];
__device__ __nv_bfloat16 g_Wlo[14712832];

// ---------------------------------------------------------------------------
// Helpers
// ---------------------------------------------------------------------------
__device__ __forceinline__ void cp_async16(u32 dst, const void* src) {
    asm volatile("cp.async.cg.shared.global [%0], [%1], 16;" :: "r"(dst), "l"(src) : "memory");
}

__device__ __forceinline__ u32 smem_u32(const void* p) {
    u32 a;
    asm("{ .reg .u64 t; cvta.to.shared.u64 t, %1; cvt.u32.u64 %0, t; }" : "=r"(a) : "l"(p));
    return a;
}

__device__ __forceinline__ void mma16816(float* c, const u32* a, const u32* b) {
    asm volatile(
        "mma.sync.aligned.m16n8k16.row.col.f32.bf16.bf16.f32 "
        "{%0,%1,%2,%3}, {%4,%5,%6,%7}, {%8,%9}, {%0,%1,%2,%3};"
        : "+f"(c[0]), "+f"(c[1]), "+f"(c[2]), "+f"(c[3])
        : "r"(a[0]), "r"(a[1]), "r"(a[2]), "r"(a[3]), "r"(b[0]), "r"(b[1]));
}

__device__ __forceinline__ void ldm_x4(u32* r, u32 addr) {
    asm volatile("ldmatrix.sync.aligned.m8n8.x4.shared.b16 {%0,%1,%2,%3}, [%4];"
        : "=r"(r[0]), "=r"(r[1]), "=r"(r[2]), "=r"(r[3]) : "r"(addr));
}

__device__ __forceinline__ float* sel_buf(int s) {
    if (s == 1) return g_bufA;
    if (s == 2) return g_bufB;
    return g_part;
}

__device__ __forceinline__ u32 pack_bf2(float a, float b) {
    __nv_bfloat162 t = __floats2bfloat162_rn(a, b);
    return *reinterpret_cast<u32*>(&t);
}

// ---------------------------------------------------------------------------
// Sampling tables for all 5 resolutions in ONE launch (86 blocks)
// ---------------------------------------------------------------------------
__global__ void make_table_all()
{
    int bi = blockIdx.x;
    int r, pb;
    if (bi < 64)      { r = 0; pb = bi; }
    else if (bi < 80) { r = 1; pb = bi - 64; }
    else if (bi < 84) { r = 2; pb = bi - 80; }
    else if (bi < 85) { r = 3; pb = bi - 84; }
    else              { r = 4; pb = bi - 85; }
    const int Hs[5]    = {128, 64, 32, 16, 8};
    const int bases[5] = {0, 147456, 184320, 193536, 195840};
    int H = Hs[r];
    int base = bases[r];
    int p = pb * blockDim.x + threadIdx.x;
    int HW = H * H;
    if (p >= HW) return;

    int y = p / H, x = p % H;
    float c = H * 0.5f - 0.5f;
    const float TWO_PI = 6.283185307179586f;
    const float PI4    = 0.7853981633974483f;
    float t = atan2f((float)x - c, (float)y - c);
    if (t < 0.f) t += TWO_PI;
    t = rintf(t * 10000.f) / 10000.f;

    #pragma unroll
    for (int k = 0; k < 9; k++) {
        float offy, offx;
        if (k == 4) { offy = 0.f; offx = 0.f; }
        else {
            int m = (k < 4) ? k : (k - 1);
            float ay = (float)(1 - k / 3);
            float ax = (float)(1 - k % 3);
            float ang = t + PI4 * (float)m;
            offy = cosf(ang) + ay;
            offx = sinf(ang) + ax;
        }
        float py = (float)(y - 1 + k / 3) + offy;
        float px = (float)(x - 1 + k % 3) + offx;
        float y0f = floorf(py), x0f = floorf(px);
        float wy = py - y0f, wx = px - x0f;
        int y0 = (int)y0f, x0 = (int)x0f;

        int4 ii; float4 ww;
        {
            int yy = y0, xx = x0;
            bool v = (yy >= 0 && yy <= H-1 && xx >= 0 && xx <= H-1);
            int yc = min(max(yy,0),H-1), xc = min(max(xx,0),H-1);
            ii.x = yc*H + xc; ww.x = v ? (1.f-wy)*(1.f-wx) : 0.f;
        }
        {
            int yy = y0, xx = x0+1;
            bool v = (yy >= 0 && yy <= H-1 && xx >= 0 && xx <= H-1);
            int yc = min(max(yy,0),H-1), xc = min(max(xx,0),H-1);
            ii.y = yc*H + xc; ww.y = v ? (1.f-wy)*wx : 0.f;
        }
        {
            int yy = y0+1, xx = x0;
            bool v = (yy >= 0 && yy <= H-1 && xx >= 0 && xx <= H-1);
            int yc = min(max(yy,0),H-1), xc = min(max(xx,0),H-1);
            ii.z = yc*H + xc; ww.z = v ? wy*(1.f-wx) : 0.f;
        }
        {
            int yy = y0+1, xx = x0+1;
            bool v = (yy >= 0 && yy <= H-1 && xx >= 0 && xx <= H-1);
            int yc = min(max(yy,0),H-1), xc = min(max(xx,0),H-1);
            ii.w = yc*H + xc; ww.w = v ? wy*wx : 0.f;
        }
        g_tIdx[base + k*HW + p] = ii;
        g_tW  [base + k*HW + p] = ww;
    }
}

// ---------------------------------------------------------------------------
// All 13 weight preps in ONE launch. K-order tap-major: kk = tap*C + c.
// src weight layout: w[o][c][tap] (O,C,3,3).
// ---------------------------------------------------------------------------
__global__ void wprep_all(const float* w0, const float* w1, const float* w2,
                          const float* w3, const float* w4, const float* w5,
                          const float* w6, const float* w7, const float* w8,
                          const float* w9, const float* w10, const float* w11,
                          const float* w12)
{
    const float* ws[13] = {w0,w1,w2,w3,w4,w5,w6,w7,w8,w9,w10,w11,w12};
    const int lC[13] = {3,64,64,128,128,256,256,256,512,512,512,512,512};
    const int lO[13] = {64,64,128,128,256,256,256,512,512,512,512,512,512};
    const int kp[13] = {64,576,576,1152,1152,2304,2304,2304,4608,4608,4608,4608,4608};

    int bi = blockIdx.x;
    int li = 0, cum = 0;
    for (li = 0; li < 13; li++) {
        int nb = (lO[li]*kp[li] + 255) >> 8;
        if (bi < cum + nb) break;
        cum += nb;
    }
    if (li >= 13) return;
    int tot = lO[li] * kp[li];
    int i = (bi - cum) * 256 + threadIdx.x;
    if (i >= tot) return;
    int woff = 0;
    for (int j = 0; j < li; j++) woff += lO[j]*kp[j];
    int C = lC[li];
    int CK = C * 9;
    int Kpad = kp[li];
    int o = i / Kpad;
    int kk = i - o * Kpad;
    float v = 0.f;
    if (kk < CK) {
        int tap = kk / C;
        int c = kk - tap * C;
        v = ws[li][(size_t)o * CK + c * 9 + tap];
    }
    __nv_bfloat16 h = __float2bfloat16(v);
    g_Whi[woff + i] = h;
    g_Wlo[woff + i] = __float2bfloat16(v - __bfloat162float(h));
}

// ---------------------------------------------------------------------------
// NHWC sampler: thread = (pixel n, 8-channel group). Per tap: 4 corner
// gathers x 8 channels as 2x LDG.128, contiguous uint4 stores to S.
// ---------------------------------------------------------------------------
__global__ void sample_nhwc(int srcSel, int tbase, int C, int HW, int Kpad, int total)
{
    int i = blockIdx.x * blockDim.x + threadIdx.x;
    if (i >= total) return;
    int G = C >> 3;
    int cg = i % G;
    int n  = i / G;
    int c0 = cg * 8;
    int b = n / HW, p = n - b * HW;
    const float* xb = ((srcSel == 1) ? g_bufA : g_bufB) + (size_t)b * HW * C;
    size_t ro = (size_t)n * Kpad;

    #pragma unroll
    for (int k = 0; k < 9; k++) {
        int4   ii = __ldg(&g_tIdx[tbase + k*HW + p]);
        float4 ww = __ldg(&g_tW  [tbase + k*HW + p]);
        const float* p0 = xb + (size_t)ii.x * C + c0;
        const float* p1 = xb + (size_t)ii.y * C + c0;
        const float* p2 = xb + (size_t)ii.z * C + c0;
        const float* p3 = xb + (size_t)ii.w * C + c0;
        float4 a0 = __ldg((const float4*)p0);
        float4 a1 = __ldg((const float4*)(p0+4));
        float4 b0 = __ldg((const float4*)p1);
        float4 b1 = __ldg((const float4*)(p1+4));
        float4 e0 = __ldg((const float4*)p2);
        float4 e1 = __ldg((const float4*)(p2+4));
        float4 d0 = __ldg((const float4*)p3);
        float4 d1 = __ldg((const float4*)(p3+4));

        float s[8];
        s[0] = ww.x*a0.x + ww.y*b0.x + ww.z*e0.x + ww.w*d0.x;
        s[1] = ww.x*a0.y + ww.y*b0.y + ww.z*e0.y + ww.w*d0.y;
        s[2] = ww.x*a0.z + ww.y*b0.z + ww.z*e0.z + ww.w*d0.z;
        s[3] = ww.x*a0.w + ww.y*b0.w + ww.z*e0.w + ww.w*d0.w;
        s[4] = ww.x*a1.x + ww.y*b1.x + ww.z*e1.x + ww.w*d1.x;
        s[5] = ww.x*a1.y + ww.y*b1.y + ww.z*e1.y + ww.w*d1.y;
        s[6] = ww.x*a1.z + ww.y*b1.z + ww.z*e1.z + ww.w*d1.z;
        s[7] = ww.x*a1.w + ww.y*b1.w + ww.z*e1.w + ww.w*d1.w;

        float hi[8], lo[8];
        #pragma unroll
        for (int j = 0; j < 8; j++) {
            __nv_bfloat16 h = __float2bfloat16(s[j]);
            hi[j] = __bfloat162float(h);
            lo[j] = s[j] - hi[j];
        }
        uint4 vh, vl;
        vh.x = pack_bf2(hi[0], hi[1]); vh.y = pack_bf2(hi[2], hi[3]);
        vh.z = pack_bf2(hi[4], hi[5]); vh.w = pack_bf2(hi[6], hi[7]);
        vl.x = pack_bf2(lo[0], lo[1]); vl.y = pack_bf2(lo[2], lo[3]);
        vl.z = pack_bf2(lo[4], lo[5]); vl.w = pack_bf2(lo[6], lo[7]);
        size_t idx = ro + k*C + c0;
        *reinterpret_cast<uint4*>(g_Shi + idx) = vh;
        *reinterpret_cast<uint4*>(g_Slo + idx) = vl;
    }
}

// ---------------------------------------------------------------------------
// L11 sampler: external NCHW input (8,3,128,128), Kpad=64, kk = tap*3 + c.
// ---------------------------------------------------------------------------
__global__ void sample_l11(const float* __restrict__ x)
{
    const int HW = 16384;
    int n = blockIdx.x * blockDim.x + threadIdx.x;
    if (n >= 8 * HW) return;
    int b = n / HW, p = n - b * HW;
    const float* xb = x + (size_t)b * 3 * HW;
    size_t ro = (size_t)n * 64;

    __nv_bfloat16 z = __float2bfloat16(0.f);
    for (int kk = 27; kk < 64; kk++) {
        g_Shi[ro + kk] = z;
        g_Slo[ro + kk] = z;
    }
    #pragma unroll
    for (int k = 0; k < 9; k++) {
        int4   ii = __ldg(&g_tIdx[k*HW + p]);
        float4 ww = __ldg(&g_tW  [k*HW + p]);
        #pragma unroll
        for (int c = 0; c < 3; c++) {
            const float* xc = xb + (size_t)c * HW;
            float s = ww.x*__ldg(xc+ii.x) + ww.y*__ldg(xc+ii.y)
                    + ww.z*__ldg(xc+ii.z) + ww.w*__ldg(xc+ii.w);
            __nv_bfloat16 h = __float2bfloat16(s);
            g_Shi[ro + k*3 + c] = h;
            g_Slo[ro + k*3 + c] = __float2bfloat16(s - __bfloat162float(h));
        }
    }
}

// ---------------------------------------------------------------------------
// mma.sync GEMM (unchanged mainloop). Epilogue writes NHWC: out[n][o].
// ---------------------------------------------------------------------------
__global__ void __launch_bounds__(256, 2)
gemm_kernel(int woff, int outSel, int O, int Npix, int Kpad, int kSplit)
{
    extern __shared__ char sm[];
    const int tid  = threadIdx.x;
    const int wid  = tid >> 5;
    const int lane = tid & 31;
    const int g    = lane >> 2;
    const int t    = lane & 3;
    const int n0 = blockIdx.x * 128;
    const int o0 = blockIdx.y * 64;
    const int kc = blockIdx.z;
    const int nCh = (Kpad / kSplit) >> 5;
    const int ci0 = kc * nCh;

    const int warpM = (wid & 3) * 32;
    const int warpN = (wid >> 2) * 32;

    const u32 sb = smem_u32(sm);

    const int aRow = ((lane >> 3) & 1) * 8 + (lane & 7);
    const int aK   = (lane >> 4) * 8;
    const int bN   = (lane >> 4) * 8 + (lane & 7);
    const int bK   = ((lane >> 3) & 1) * 8;

    float acc[2][4][4];
    #pragma unroll
    for (int mt = 0; mt < 2; mt++)
        #pragma unroll
        for (int nt = 0; nt < 4; nt++)
            #pragma unroll
            for (int r = 0; r < 4; r++) acc[mt][nt][r] = 0.f;

    const int nGran = 1536;

    for (int i = 0; i < nCh; i++) {
        int s = i & 1;
        if (i + 1 < nCh) {
            int colOff = (ci0 + i + 1) * 32;
            u32 stBase = sb + (u32)((1 - s) * 30720);
            for (int gr = tid; gr < nGran; gr += 256) {
                if (gr < 512) {
                    int row = gr >> 2, gi = gr & 3;
                    cp_async16(stBase + (u32)(row*80 + gi*16),
                               g_Shi + (size_t)(n0+row)*Kpad + colOff + gi*8);
                } else if (gr < 1024) {
                    int gg = gr - 512;
                    int row = gg >> 2, gi = gg & 3;
                    cp_async16(stBase + (u32)(10240 + row*80 + gi*16),
                               g_Slo + (size_t)(n0+row)*Kpad + colOff + gi*8);
                } else if (gr < 1280) {
                    int gg = gr - 1024;
                    int row = gg >> 2, gi = gg & 3;
                    cp_async16(stBase + (u32)(20480 + row*80 + gi*16),
                               g_Whi + woff + (size_t)(o0+row)*Kpad + colOff + gi*8);
                } else {
                    int gg = gr - 1280;
                    int row = gg >> 2, gi = gg & 3;
                    cp_async16(stBase + (u32)(25600 + row*80 + gi*16),
                               g_Wlo + woff + (size_t)(o0+row)*Kpad + colOff + gi*8);
                }
            }
            asm volatile("cp.async.commit_group;" ::: "memory");
            asm volatile("cp.async.wait_group 1;" ::: "memory");
        } else {
            asm volatile("cp.async.wait_group 0;" ::: "memory");
        }
        if (i == 0) {
            int colOff = ci0 * 32;
            u32 stBase = sb;
            for (int gr = tid; gr < nGran; gr += 256) {
                if (gr < 512) {
                    int row = gr >> 2, gi = gr & 3;
                    cp_async16(stBase + (u32)(row*80 + gi*16),
                               g_Shi + (size_t)(n0+row)*Kpad + colOff + gi*8);
                } else if (gr < 1024) {
                    int gg = gr - 512;
                    int row = gg >> 2, gi = gg & 3;
                    cp_async16(stBase + (u32)(10240 + row*80 + gi*16),
                               g_Slo + (size_t)(n0+row)*Kpad + colOff + gi*8);
                } else if (gr < 1280) {
                    int gg = gr - 1024;
                    int row = gg >> 2, gi = gg & 3;
                    cp_async16(stBase + (u32)(20480 + row*80 + gi*16),
                               g_Whi + woff + (size_t)(o0+row)*Kpad + colOff + gi*8);
                } else {
                    int gg = gr - 1280;
                    int row = gg >> 2, gi = gg & 3;
                    cp_async16(stBase + (u32)(25600 + row*80 + gi*16),
                               g_Wlo + woff + (size_t)(o0+row)*Kpad + colOff + gi*8);
                }
            }
            asm volatile("cp.async.commit_group;" ::: "memory");
            asm volatile("cp.async.wait_group 0;" ::: "memory");
        }
        __syncthreads();

        u32 stA_h = sb + (u32)(s * 30720);
        u32 stA_l = stA_h + 10240u;
        u32 stB_h = stA_h + 20480u;
        u32 stB_l = stA_h + 25600u;

        #pragma unroll
        for (int k0 = 0; k0 < 32; k0 += 16) {
            u32 ah[2][4], al[2][4], bh2[2][4], bl2[2][4];
            #pragma unroll
            for (int mt = 0; mt < 2; mt++) {
                u32 off = (u32)((warpM + mt*16 + aRow)*80 + (k0 + aK)*2);
                ldm_x4(ah[mt], stA_h + off);
                ldm_x4(al[mt], stA_l + off);
            }
            #pragma unroll
            for (int pr = 0; pr < 2; pr++) {
                u32 off = (u32)((warpN + pr*16 + bN)*80 + (k0 + bK)*2);
                ldm_x4(bh2[pr], stB_h + off);
                ldm_x4(bl2[pr], stB_l + off);
            }
            #pragma unroll
            for (int mt = 0; mt < 2; mt++) {
                #pragma unroll
                for (int nt = 0; nt < 4; nt++) {
                    const u32* bh_ = &bh2[nt >> 1][(nt & 1) * 2];
                    const u32* bl_ = &bl2[nt >> 1][(nt & 1) * 2];
                    mma16816(acc[mt][nt], ah[mt], bh_);
                    mma16816(acc[mt][nt], ah[mt], bl_);
                    mma16816(acc[mt][nt], al[mt], bh_);
                }
            }
        }
        __syncthreads();
    }

    // ---- epilogue: NHWC stores out[n*O + o] ----
    float* ob = sel_buf(outSel);
    int doRelu = 1;
    if (outSel == 3) {
        ob = g_part + (size_t)kc * (size_t)O * (size_t)Npix;
        doRelu = 0;
    }
    #pragma unroll
    for (int mt = 0; mt < 2; mt++) {
        #pragma unroll
        for (int nt = 0; nt < 4; nt++) {
            int pr0 = n0 + warpM + mt*16 + g;
            int pr1 = pr0 + 8;
            int oc  = o0 + warpN + nt*8 + 2*t;
            float v0 = acc[mt][nt][0];
            float v1 = acc[mt][nt][1];
            float v2 = acc[mt][nt][2];
            float v3 = acc[mt][nt][3];
            if (doRelu) {
                v0 = fmaxf(v0, 0.f); v1 = fmaxf(v1, 0.f);
                v2 = fmaxf(v2, 0.f); v3 = fmaxf(v3, 0.f);
            }
            ob[(size_t)pr0 * O + oc]     = v0;
            ob[(size_t)pr0 * O + oc + 1] = v1;
            ob[(size_t)pr1 * O + oc]     = v2;
            ob[(size_t)pr1 * O + oc + 1] = v3;
        }
    }
}

// ---------------------------------------------------------------------------
// Split-K reduce + ReLU (deterministic)
// ---------------------------------------------------------------------------
__global__ void reduce_relu_kernel(int outSel, int n, int kSplit)
{
    int i = blockIdx.x * blockDim.x + threadIdx.x;
    if (i >= n) return;
    float s = 0.f;
    for (int j = 0; j < kSplit; j++) s += g_part[(size_t)j*n + i];
    float* out = sel_buf(outSel);
    out[i] = fmaxf(s, 0.f);
}

// ---------------------------------------------------------------------------
// 2x2 max pool, NHWC: (8,H,H,C) -> (8,H/2,H/2,C)
// ---------------------------------------------------------------------------
__global__ void pool_kernel(int inSel, int outSel, int C, int H)
{
    const float* in = sel_buf(inSel);
    float* out = sel_buf(outSel);
    int Ho = H / 2;
    int total = 8 * Ho * Ho * C;
    int i = blockIdx.x * blockDim.x + threadIdx.x;
    if (i >= total) return;
    int c = i % C; int t = i / C;
    int xo = t % Ho; t /= Ho;
    int yo = t % Ho; int b = t / Ho;
    const float* ib = in + (((size_t)b*H + yo*2)*H + xo*2)*C + c;
    float v0 = ib[0];
    float v1 = ib[C];
    float v2 = ib[(size_t)H*C];
    float v3 = ib[(size_t)H*C + C];
    out[i] = fmaxf(fmaxf(v0, v1), fmaxf(v2, v3));
}

// NHWC (8,4,4,512) in g_bufB -> (8,512) mean in g_vec
__global__ void avg_kernel()
{
    int i = blockIdx.x * blockDim.x + threadIdx.x;
    if (i >= 8*512) return;
    int b = i / 512, c = i % 512;
    float s = 0.f;
    #pragma unroll
    for (int j = 0; j < 16; j++) s += g_bufB[((size_t)b*16 + j)*512 + c];
    g_vec[i] = s * (1.f/16.f);
}

// ---------------------------------------------------------------------------
// FC layers
// ---------------------------------------------------------------------------
__global__ void fc_kernel(const float* __restrict__ W, const float* __restrict__ bias,
                          float* dout, int stage, int K, int O)
{
    const float* x = g_vec;
    if (stage == 1) x = g_fc1o;
    if (stage == 2) x = g_fc2o;
    float* y = g_fc1o;
    if (stage == 1) y = g_fc2o;
    if (stage == 2) y = dout;
    int relu = (stage < 2) ? 1 : 0;

    int o = blockIdx.x;
    float acc[8];
    #pragma unroll
    for (int i = 0; i < 8; i++) acc[i] = 0.f;
    const float* wr = W + (size_t)o * K;
    for (int k = threadIdx.x; k < K; k += 128) {
        float wv = wr[k];
        #pragma unroll
        for (int b = 0; b < 8; b++) acc[b] = fmaf(x[(size_t)b*K + k], wv, acc[b]);
    }
    __shared__ float red[8][128];
    #pragma unroll
    for (int b = 0; b < 8; b++) red[b][threadIdx.x] = acc[b];
    __syncthreads();
    for (int s = 64; s > 0; s >>= 1) {
        if (threadIdx.x < s) {
            #pragma unroll
            for (int b = 0; b < 8; b++)
                red[b][threadIdx.x] += red[b][threadIdx.x + s];
        }
        __syncthreads();
    }
    if (threadIdx.x < 8) {
        int b = threadIdx.x;
        float v = red[b][0] + bias[o];
        if (relu) v = fmaxf(v, 0.f);
        y[(size_t)b*O + o] = v;
    }
}

// ---------------------------------------------------------------------------
// Host orchestration
// ---------------------------------------------------------------------------
extern "C" void kernel_launch(void* const* d_in, const int* in_sizes, int n_in,
                              void* d_out, int out_size)
{
    const float* x = (const float*)d_in[0];
    const float* w[13];
    for (int i = 0; i < 13; i++) w[i] = (const float*)d_in[1+i];
    const float* fc1w = (const float*)d_in[14];
    const float* fc1b = (const float*)d_in[15];
    const float* fc2w = (const float*)d_in[16];
    const float* fc2b = (const float*)d_in[17];
    const float* fc3w = (const float*)d_in[18];
    const float* fc3b = (const float*)d_in[19];

    cudaFuncSetAttribute(gemm_kernel,
                         cudaFuncAttributeMaxDynamicSharedMemorySize, 61440);

    make_table_all<<<86, 256>>>();

    const int lC[13] = {3,64,64,128,128,256,256,256,512,512,512,512,512};
    const int lO[13] = {64,64,128,128,256,256,256,512,512,512,512,512,512};
    int kpad[13];
    int woff[13];
    int wacc = 0;
    int nblk = 0;
    for (int i = 0; i < 13; i++) {
        kpad[i] = ((lC[i]*9 + 63) / 64) * 64;
        woff[i] = wacc;
        wacc += lO[i] * kpad[i];
        nblk += (lO[i]*kpad[i] + 255) / 256;
    }
    wprep_all<<<nblk, 256>>>(w[0],w[1],w[2],w[3],w[4],w[5],w[6],
                             w[7],w[8],w[9],w[10],w[11],w[12]);

    const int tbase[5] = {0, 147456, 184320, 193536, 195840};
    const int lH[13]   = {128,128,64,64,32,32,32,16,16,16,8,8,8};
    const int lKS[13]  = {1,1,1,1,1,1,1,2,2,2,8,8,8};
    const int srcSel[13] = {0,1,1,2,2,1,2,2,1,2,2,1,2};
    const int dstSel[13] = {1,2,2,1,1,2,1,1,2,1,1,2,1};

    for (int li = 0; li < 13; li++) {
        int C = lC[li], O = lO[li], H = lH[li], kSplit = lKS[li];
        int HW = H * H;
        int Kpad = kpad[li];
        int ti = 4;
        if (HW == 16384) ti = 0;
        else if (HW == 4096) ti = 1;
        else if (HW == 1024) ti = 2;
        else if (HW == 256) ti = 3;

        int Npix = 8 * HW;
        if (li == 0) {
            sample_l11<<<(Npix + 255)/256, 256>>>(x);
        } else {
            int total = Npix * (C >> 3);
            sample_nhwc<<<(total + 255)/256, 256>>>(srcSel[li], tbase[ti],
                                                    C, HW, Kpad, total);
        }

        dim3 grid(Npix/128, O/64, kSplit);
        int outSel = dstSel[li];
        if (kSplit > 1) outSel = 3;
        gemm_kernel<<<grid, 256, 61440>>>(woff[li], outSel, O, Npix, Kpad, kSplit);
        if (kSplit > 1) {
            int n = O * Npix;
            reduce_relu_kernel<<<(n + 255)/256, 256>>>(dstSel[li], n, kSplit);
        }

        if (li == 1)  pool_kernel<<<(8*64*64*64  + 255)/256, 256>>>(2, 1, 64, 128);
        if (li == 3)  pool_kernel<<<(8*128*32*32 + 255)/256, 256>>>(1, 2, 128, 64);
        if (li == 6)  pool_kernel<<<(8*256*16*16 + 255)/256, 256>>>(1, 2, 256, 32);
        if (li == 9)  pool_kernel<<<(8*512*8*8   + 255)/256, 256>>>(1, 2, 512, 16);
        if (li == 12) pool_kernel<<<(8*512*4*4   + 255)/256, 256>>>(1, 2, 512, 8);
    }

    avg_kernel<<<(8*512 + 255)/256, 256>>>();

    fc_kernel<<<4096, 128>>>(fc1w, fc1b, (float*)d_out, 0, 512, 4096);
    fc_kernel<<<4096, 128>>>(fc2w, fc2b, (float*)d_out, 1, 4096, 4096);
    fc_kernel<<<30,   128>>>(fc3w, fc3b, (float*)d_out, 2, 4096, 30);
}

// round 15
// speedup vs baseline: 2.9238x; 1.0724x over previous
#include <cuda_runtime.h>
#include <cuda_bf16.h>
#include <cstdint>
#include <math.h>

typedef unsigned int       u32;
typedef unsigned long long u64;

// ---------------------------------------------------------------------------
// Scratch (static device globals - no allocations anywhere)
// All activations are NHWC: [b][p][c], c contiguous.
// ---------------------------------------------------------------------------
#define MAXACT (8*64*128*128)
__device__ float  g_bufA[MAXACT];
__device__ float  g_bufB[MAXACT];
__device__ float  g_part[4194304];
__device__ int4   g_tIdx[196416];
__device__ float4 g_tW  [196416];
__device__ float  g_vec[8*512];
__device__ float  g_fc1o[8*4096];
__device__ float  g_fc2o[8*4096];
// K-dim order is tap-major: kk = tap*C + c  (S and W agree)
__device__ __nv_bfloat16 g_Shi[75497472];
__device__ __nv_bfloat16 g_Slo[75497472];
__device__ __nv_bfloat16 g_Whi[14712832];
__device__ __nv_bfloat16 g_Wlo[14712832];

// ---------------------------------------------------------------------------
// Helpers
// ---------------------------------------------------------------------------
__device__ __forceinline__ void cp_async16(u32 dst, const void* src) {
    asm volatile("cp.async.cg.shared.global [%0], [%1], 16;" :: "r"(dst), "l"(src) : "memory");
}

__device__ __forceinline__ u32 smem_u32(const void* p) {
    u32 a;
    asm("{ .reg .u64 t; cvta.to.shared.u64 t, %1; cvt.u32.u64 %0, t; }" : "=r"(a) : "l"(p));
    return a;
}

__device__ __forceinline__ void mma16816(float* c, const u32* a, const u32* b) {
    asm volatile(
        "mma.sync.aligned.m16n8k16.row.col.f32.bf16.bf16.f32 "
        "{%0,%1,%2,%3}, {%4,%5,%6,%7}, {%8,%9}, {%0,%1,%2,%3};"
        : "+f"(c[0]), "+f"(c[1]), "+f"(c[2]), "+f"(c[3])
        : "r"(a[0]), "r"(a[1]), "r"(a[2]), "r"(a[3]), "r"(b[0]), "r"(b[1]));
}

__device__ __forceinline__ void ldm_x4(u32* r, u32 addr) {
    asm volatile("ldmatrix.sync.aligned.m8n8.x4.shared.b16 {%0,%1,%2,%3}, [%4];"
        : "=r"(r[0]), "=r"(r[1]), "=r"(r[2]), "=r"(r[3]) : "r"(addr));
}

__device__ __forceinline__ float* sel_buf(int s) {
    if (s == 1) return g_bufA;
    if (s == 2) return g_bufB;
    return g_part;
}

__device__ __forceinline__ u32 pack_bf2(float a, float b) {
    __nv_bfloat162 t = __floats2bfloat162_rn(a, b);
    return *reinterpret_cast<u32*>(&t);
}

__device__ __forceinline__ u32 pack_raw(__nv_bfloat16 a, __nv_bfloat16 b) {
    u32 ua = *reinterpret_cast<unsigned short*>(&a);
    u32 ub = *reinterpret_cast<unsigned short*>(&b);
    return ua | (ub << 16);
}

// ---------------------------------------------------------------------------
// Sampling tables for all 5 resolutions in ONE launch (86 blocks)
// ---------------------------------------------------------------------------
__global__ void make_table_all()
{
    int bi = blockIdx.x;
    int r, pb;
    if (bi < 64)      { r = 0; pb = bi; }
    else if (bi < 80) { r = 1; pb = bi - 64; }
    else if (bi < 84) { r = 2; pb = bi - 80; }
    else if (bi < 85) { r = 3; pb = bi - 84; }
    else              { r = 4; pb = bi - 85; }
    const int Hs[5]    = {128, 64, 32, 16, 8};
    const int bases[5] = {0, 147456, 184320, 193536, 195840};
    int H = Hs[r];
    int base = bases[r];
    int p = pb * blockDim.x + threadIdx.x;
    int HW = H * H;
    if (p >= HW) return;

    int y = p / H, x = p % H;
    float c = H * 0.5f - 0.5f;
    const float TWO_PI = 6.283185307179586f;
    const float PI4    = 0.7853981633974483f;
    float t = atan2f((float)x - c, (float)y - c);
    if (t < 0.f) t += TWO_PI;
    t = rintf(t * 10000.f) / 10000.f;

    #pragma unroll
    for (int k = 0; k < 9; k++) {
        float offy, offx;
        if (k == 4) { offy = 0.f; offx = 0.f; }
        else {
            int m = (k < 4) ? k : (k - 1);
            float ay = (float)(1 - k / 3);
            float ax = (float)(1 - k % 3);
            float ang = t + PI4 * (float)m;
            offy = cosf(ang) + ay;
            offx = sinf(ang) + ax;
        }
        float py = (float)(y - 1 + k / 3) + offy;
        float px = (float)(x - 1 + k % 3) + offx;
        float y0f = floorf(py), x0f = floorf(px);
        float wy = py - y0f, wx = px - x0f;
        int y0 = (int)y0f, x0 = (int)x0f;

        int4 ii; float4 ww;
        {
            int yy = y0, xx = x0;
            bool v = (yy >= 0 && yy <= H-1 && xx >= 0 && xx <= H-1);
            int yc = min(max(yy,0),H-1), xc = min(max(xx,0),H-1);
            ii.x = yc*H + xc; ww.x = v ? (1.f-wy)*(1.f-wx) : 0.f;
        }
        {
            int yy = y0, xx = x0+1;
            bool v = (yy >= 0 && yy <= H-1 && xx >= 0 && xx <= H-1);
            int yc = min(max(yy,0),H-1), xc = min(max(xx,0),H-1);
            ii.y = yc*H + xc; ww.y = v ? (1.f-wy)*wx : 0.f;
        }
        {
            int yy = y0+1, xx = x0;
            bool v = (yy >= 0 && yy <= H-1 && xx >= 0 && xx <= H-1);
            int yc = min(max(yy,0),H-1), xc = min(max(xx,0),H-1);
            ii.z = yc*H + xc; ww.z = v ? wy*(1.f-wx) : 0.f;
        }
        {
            int yy = y0+1, xx = x0+1;
            bool v = (yy >= 0 && yy <= H-1 && xx >= 0 && xx <= H-1);
            int yc = min(max(yy,0),H-1), xc = min(max(xx,0),H-1);
            ii.w = yc*H + xc; ww.w = v ? wy*wx : 0.f;
        }
        g_tIdx[base + k*HW + p] = ii;
        g_tW  [base + k*HW + p] = ww;
    }
}

// ---------------------------------------------------------------------------
// Weight prep over layer range [liBeg, liEnd). K-order tap-major.
// src weight layout: w[o][c][tap] (O,C,3,3).
// ---------------------------------------------------------------------------
__global__ void wprep_range(const float* w0, const float* w1, const float* w2,
                            const float* w3, const float* w4, const float* w5,
                            const float* w6, const float* w7, const float* w8,
                            const float* w9, const float* w10, const float* w11,
                            const float* w12, int liBeg, int liEnd)
{
    const float* ws[13] = {w0,w1,w2,w3,w4,w5,w6,w7,w8,w9,w10,w11,w12};
    const int lC[13] = {3,64,64,128,128,256,256,256,512,512,512,512,512};
    const int lO[13] = {64,64,128,128,256,256,256,512,512,512,512,512,512};
    const int kp[13] = {64,576,576,1152,1152,2304,2304,2304,4608,4608,4608,4608,4608};

    int bi = blockIdx.x;
    int li, cum = 0;
    for (li = liBeg; li < liEnd; li++) {
        int nb = (lO[li]*kp[li] + 255) >> 8;
        if (bi < cum + nb) break;
        cum += nb;
    }
    if (li >= liEnd) return;
    int tot = lO[li] * kp[li];
    int i = (bi - cum) * 256 + threadIdx.x;
    if (i >= tot) return;
    int woff = 0;
    for (int j = 0; j < li; j++) woff += lO[j]*kp[j];
    int C = lC[li];
    int CK = C * 9;
    int Kpad = kp[li];
    int o = i / Kpad;
    int kk = i - o * Kpad;
    float v = 0.f;
    if (kk < CK) {
        int tap = kk / C;
        int c = kk - tap * C;
        v = ws[li][(size_t)o * CK + c * 9 + tap];
    }
    __nv_bfloat16 h = __float2bfloat16(v);
    g_Whi[woff + i] = h;
    g_Wlo[woff + i] = __float2bfloat16(v - __bfloat162float(h));
}

// ---------------------------------------------------------------------------
// L11 sampler: external NCHW input (8,3,128,128), Kpad=64, kk = tap*3 + c.
// All 64 k-entries built in registers, stored as vectorized uint4.
// ---------------------------------------------------------------------------
__global__ void sample_l11(const float* __restrict__ x)
{
    const int HW = 16384;
    int n = blockIdx.x * blockDim.x + threadIdx.x;
    if (n >= 8 * HW) return;
    int b = n / HW, p = n - b * HW;
    const float* xb = x + (size_t)b * 3 * HW;

    float s[27];
    #pragma unroll
    for (int k = 0; k < 9; k++) {
        int4   ii = __ldg(&g_tIdx[k*HW + p]);
        float4 ww = __ldg(&g_tW  [k*HW + p]);
        #pragma unroll
        for (int c = 0; c < 3; c++) {
            const float* xc = xb + (size_t)c * HW;
            s[k*3+c] = ww.x*__ldg(xc+ii.x) + ww.y*__ldg(xc+ii.y)
                     + ww.z*__ldg(xc+ii.z) + ww.w*__ldg(xc+ii.w);
        }
    }
    u32 vh[16], vl[16];
    #pragma unroll
    for (int j = 0; j < 16; j++) {
        float a  = (2*j   < 27) ? s[2*j]   : 0.f;
        float b2 = (2*j+1 < 27) ? s[2*j+1] : 0.f;
        __nv_bfloat16 ha = __float2bfloat16(a);
        __nv_bfloat16 hb = __float2bfloat16(b2);
        vh[j] = pack_raw(ha, hb);
        vl[j] = pack_bf2(a - __bfloat162float(ha), b2 - __bfloat162float(hb));
    }
    size_t ro = (size_t)n * 64;
    uint4* dh = reinterpret_cast<uint4*>(g_Shi + ro);
    uint4* dl = reinterpret_cast<uint4*>(g_Slo + ro);
    #pragma unroll
    for (int q = 0; q < 4; q++) {
        dh[q] = make_uint4(vh[4*q], vh[4*q+1], vh[4*q+2], vh[4*q+3]);
        dl[q] = make_uint4(vl[4*q], vl[4*q+1], vl[4*q+2], vl[4*q+3]);
    }
}

// ---------------------------------------------------------------------------
// NHWC sampler v2: block = P pixels x G channel-groups (P=256/G, G=C/8).
// Tables staged in smem once per block (broadcast reads). Tap 4 is the exact
// identity (offset 0, weight 1) -> direct copy fast path.
// ---------------------------------------------------------------------------
__global__ void __launch_bounds__(256)
sample_nhwc(int srcSel, int tbase, int C, int HW, int Kpad, int npix)
{
    __shared__ int4   sIdx[288];   // 9 * P, P <= 32
    __shared__ float4 sWw [288];
    const int G = C >> 3;
    const int P = 256 / G;
    const int n0 = blockIdx.x * P;
    const int b  = n0 / HW;
    const int p0 = n0 - b * HW;    // P divides HW for all layers

    for (int e = threadIdx.x; e < 9*P; e += 256) {
        int k = e / P, pl = e - (e / P) * P;
        sIdx[e] = g_tIdx[tbase + k*HW + p0 + pl];
        sWw[e]  = g_tW  [tbase + k*HW + p0 + pl];
    }
    __syncthreads();

    const int cg = threadIdx.x % G;
    const int pl = threadIdx.x / G;
    const int c0 = cg * 8;
    const float* xb = ((srcSel == 1) ? g_bufA : g_bufB) + (size_t)b * HW * C;
    size_t ro = (size_t)(n0 + pl) * Kpad + c0;

    #pragma unroll
    for (int k = 0; k < 9; k++) {
        float s[8];
        if (k == 4) {
            const float* pc = xb + (size_t)(p0 + pl) * C + c0;
            float4 a0 = __ldg((const float4*)pc);
            float4 a1 = __ldg((const float4*)(pc+4));
            s[0]=a0.x; s[1]=a0.y; s[2]=a0.z; s[3]=a0.w;
            s[4]=a1.x; s[5]=a1.y; s[6]=a1.z; s[7]=a1.w;
        } else {
            int4   ii = sIdx[k*P + pl];
            float4 ww = sWw [k*P + pl];
            const float* q0 = xb + (size_t)ii.x * C + c0;
            const float* q1 = xb + (size_t)ii.y * C + c0;
            const float* q2 = xb + (size_t)ii.z * C + c0;
            const float* q3 = xb + (size_t)ii.w * C + c0;
            float4 a0 = __ldg((const float4*)q0);
            float4 a1 = __ldg((const float4*)(q0+4));
            float4 b0 = __ldg((const float4*)q1);
            float4 b1 = __ldg((const float4*)(q1+4));
            float4 e0 = __ldg((const float4*)q2);
            float4 e1 = __ldg((const float4*)(q2+4));
            float4 d0 = __ldg((const float4*)q3);
            float4 d1 = __ldg((const float4*)(q3+4));
            s[0] = ww.x*a0.x + ww.y*b0.x + ww.z*e0.x + ww.w*d0.x;
            s[1] = ww.x*a0.y + ww.y*b0.y + ww.z*e0.y + ww.w*d0.y;
            s[2] = ww.x*a0.z + ww.y*b0.z + ww.z*e0.z + ww.w*d0.z;
            s[3] = ww.x*a0.w + ww.y*b0.w + ww.z*e0.w + ww.w*d0.w;
            s[4] = ww.x*a1.x + ww.y*b1.x + ww.z*e1.x + ww.w*d1.x;
            s[5] = ww.x*a1.y + ww.y*b1.y + ww.z*e1.y + ww.w*d1.y;
            s[6] = ww.x*a1.z + ww.y*b1.z + ww.z*e1.z + ww.w*d1.z;
            s[7] = ww.x*a1.w + ww.y*b1.w + ww.z*e1.w + ww.w*d1.w;
        }
        float hi[8], lo[8];
        #pragma unroll
        for (int j = 0; j < 8; j++) {
            __nv_bfloat16 h = __float2bfloat16(s[j]);
            hi[j] = __bfloat162float(h);
            lo[j] = s[j] - hi[j];
        }
        uint4 vh, vl;
        vh.x = pack_bf2(hi[0], hi[1]); vh.y = pack_bf2(hi[2], hi[3]);
        vh.z = pack_bf2(hi[4], hi[5]); vh.w = pack_bf2(hi[6], hi[7]);
        vl.x = pack_bf2(lo[0], lo[1]); vl.y = pack_bf2(lo[2], lo[3]);
        vl.z = pack_bf2(lo[4], lo[5]); vl.w = pack_bf2(lo[6], lo[7]);
        *reinterpret_cast<uint4*>(g_Shi + ro + k*C) = vh;
        *reinterpret_cast<uint4*>(g_Slo + ro + k*C) = vl;
    }
}

// ---------------------------------------------------------------------------
// mma.sync GEMM (unchanged). Epilogue writes NHWC: out[n][o].
// ---------------------------------------------------------------------------
__global__ void __launch_bounds__(256, 2)
gemm_kernel(int woff, int outSel, int O, int Npix, int Kpad, int kSplit)
{
    extern __shared__ char sm[];
    const int tid  = threadIdx.x;
    const int wid  = tid >> 5;
    const int lane = tid & 31;
    const int g    = lane >> 2;
    const int t    = lane & 3;
    const int n0 = blockIdx.x * 128;
    const int o0 = blockIdx.y * 64;
    const int kc = blockIdx.z;
    const int nCh = (Kpad / kSplit) >> 5;
    const int ci0 = kc * nCh;

    const int warpM = (wid & 3) * 32;
    const int warpN = (wid >> 2) * 32;

    const u32 sb = smem_u32(sm);

    const int aRow = ((lane >> 3) & 1) * 8 + (lane & 7);
    const int aK   = (lane >> 4) * 8;
    const int bN   = (lane >> 4) * 8 + (lane & 7);
    const int bK   = ((lane >> 3) & 1) * 8;

    float acc[2][4][4];
    #pragma unroll
    for (int mt = 0; mt < 2; mt++)
        #pragma unroll
        for (int nt = 0; nt < 4; nt++)
            #pragma unroll
            for (int r = 0; r < 4; r++) acc[mt][nt][r] = 0.f;

    const int nGran = 1536;

    for (int i = 0; i < nCh; i++) {
        int s = i & 1;
        if (i + 1 < nCh) {
            int colOff = (ci0 + i + 1) * 32;
            u32 stBase = sb + (u32)((1 - s) * 30720);
            for (int gr = tid; gr < nGran; gr += 256) {
                if (gr < 512) {
                    int row = gr >> 2, gi = gr & 3;
                    cp_async16(stBase + (u32)(row*80 + gi*16),
                               g_Shi + (size_t)(n0+row)*Kpad + colOff + gi*8);
                } else if (gr < 1024) {
                    int gg = gr - 512;
                    int row = gg >> 2, gi = gg & 3;
                    cp_async16(stBase + (u32)(10240 + row*80 + gi*16),
                               g_Slo + (size_t)(n0+row)*Kpad + colOff + gi*8);
                } else if (gr < 1280) {
                    int gg = gr - 1024;
                    int row = gg >> 2, gi = gg & 3;
                    cp_async16(stBase + (u32)(20480 + row*80 + gi*16),
                               g_Whi + woff + (size_t)(o0+row)*Kpad + colOff + gi*8);
                } else {
                    int gg = gr - 1280;
                    int row = gg >> 2, gi = gg & 3;
                    cp_async16(stBase + (u32)(25600 + row*80 + gi*16),
                               g_Wlo + woff + (size_t)(o0+row)*Kpad + colOff + gi*8);
                }
            }
            asm volatile("cp.async.commit_group;" ::: "memory");
            asm volatile("cp.async.wait_group 1;" ::: "memory");
        } else {
            asm volatile("cp.async.wait_group 0;" ::: "memory");
        }
        if (i == 0) {
            int colOff = ci0 * 32;
            u32 stBase = sb;
            for (int gr = tid; gr < nGran; gr += 256) {
                if (gr < 512) {
                    int row = gr >> 2, gi = gr & 3;
                    cp_async16(stBase + (u32)(row*80 + gi*16),
                               g_Shi + (size_t)(n0+row)*Kpad + colOff + gi*8);
                } else if (gr < 1024) {
                    int gg = gr - 512;
                    int row = gg >> 2, gi = gg & 3;
                    cp_async16(stBase + (u32)(10240 + row*80 + gi*16),
                               g_Slo + (size_t)(n0+row)*Kpad + colOff + gi*8);
                } else if (gr < 1280) {
                    int gg = gr - 1024;
                    int row = gg >> 2, gi = gg & 3;
                    cp_async16(stBase + (u32)(20480 + row*80 + gi*16),
                               g_Whi + woff + (size_t)(o0+row)*Kpad + colOff + gi*8);
                } else {
                    int gg = gr - 1280;
                    int row = gg >> 2, gi = gg & 3;
                    cp_async16(stBase + (u32)(25600 + row*80 + gi*16),
                               g_Wlo + woff + (size_t)(o0+row)*Kpad + colOff + gi*8);
                }
            }
            asm volatile("cp.async.commit_group;" ::: "memory");
            asm volatile("cp.async.wait_group 0;" ::: "memory");
        }
        __syncthreads();

        u32 stA_h = sb + (u32)(s * 30720);
        u32 stA_l = stA_h + 10240u;
        u32 stB_h = stA_h + 20480u;
        u32 stB_l = stA_h + 25600u;

        #pragma unroll
        for (int k0 = 0; k0 < 32; k0 += 16) {
            u32 ah[2][4], al[2][4], bh2[2][4], bl2[2][4];
            #pragma unroll
            for (int mt = 0; mt < 2; mt++) {
                u32 off = (u32)((warpM + mt*16 + aRow)*80 + (k0 + aK)*2);
                ldm_x4(ah[mt], stA_h + off);
                ldm_x4(al[mt], stA_l + off);
            }
            #pragma unroll
            for (int pr = 0; pr < 2; pr++) {
                u32 off = (u32)((warpN + pr*16 + bN)*80 + (k0 + bK)*2);
                ldm_x4(bh2[pr], stB_h + off);
                ldm_x4(bl2[pr], stB_l + off);
            }
            #pragma unroll
            for (int mt = 0; mt < 2; mt++) {
                #pragma unroll
                for (int nt = 0; nt < 4; nt++) {
                    const u32* bh_ = &bh2[nt >> 1][(nt & 1) * 2];
                    const u32* bl_ = &bl2[nt >> 1][(nt & 1) * 2];
                    mma16816(acc[mt][nt], ah[mt], bh_);
                    mma16816(acc[mt][nt], ah[mt], bl_);
                    mma16816(acc[mt][nt], al[mt], bh_);
                }
            }
        }
        __syncthreads();
    }

    float* ob = sel_buf(outSel);
    int doRelu = 1;
    if (outSel == 3) {
        ob = g_part + (size_t)kc * (size_t)O * (size_t)Npix;
        doRelu = 0;
    }
    #pragma unroll
    for (int mt = 0; mt < 2; mt++) {
        #pragma unroll
        for (int nt = 0; nt < 4; nt++) {
            int pr0 = n0 + warpM + mt*16 + g;
            int pr1 = pr0 + 8;
            int oc  = o0 + warpN + nt*8 + 2*t;
            float v0 = acc[mt][nt][0];
            float v1 = acc[mt][nt][1];
            float v2 = acc[mt][nt][2];
            float v3 = acc[mt][nt][3];
            if (doRelu) {
                v0 = fmaxf(v0, 0.f); v1 = fmaxf(v1, 0.f);
                v2 = fmaxf(v2, 0.f); v3 = fmaxf(v3, 0.f);
            }
            ob[(size_t)pr0 * O + oc]     = v0;
            ob[(size_t)pr0 * O + oc + 1] = v1;
            ob[(size_t)pr1 * O + oc]     = v2;
            ob[(size_t)pr1 * O + oc + 1] = v3;
        }
    }
}

// ---------------------------------------------------------------------------
// Split-K reduce + ReLU (deterministic)
// ---------------------------------------------------------------------------
__global__ void reduce_relu_kernel(int outSel, int n, int kSplit)
{
    int i = blockIdx.x * blockDim.x + threadIdx.x;
    if (i >= n) return;
    float s = 0.f;
    for (int j = 0; j < kSplit; j++) s += g_part[(size_t)j*n + i];
    float* out = sel_buf(outSel);
    out[i] = fmaxf(s, 0.f);
}

// ---------------------------------------------------------------------------
// 2x2 max pool, NHWC: (8,H,H,C) -> (8,H/2,H/2,C)
// ---------------------------------------------------------------------------
__global__ void pool_kernel(int inSel, int outSel, int C, int H)
{
    const float* in = sel_buf(inSel);
    float* out = sel_buf(outSel);
    int Ho = H / 2;
    int total = 8 * Ho * Ho * C;
    int i = blockIdx.x * blockDim.x + threadIdx.x;
    if (i >= total) return;
    int c = i % C; int t = i / C;
    int xo = t % Ho; t /= Ho;
    int yo = t % Ho; int b = t / Ho;
    const float* ib = in + (((size_t)b*H + yo*2)*H + xo*2)*C + c;
    float v0 = ib[0];
    float v1 = ib[C];
    float v2 = ib[(size_t)H*C];
    float v3 = ib[(size_t)H*C + C];
    out[i] = fmaxf(fmaxf(v0, v1), fmaxf(v2, v3));
}

// NHWC (8,4,4,512) in g_bufB -> (8,512) mean in g_vec
__global__ void avg_kernel()
{
    int i = blockIdx.x * blockDim.x + threadIdx.x;
    if (i >= 8*512) return;
    int b = i / 512, c = i % 512;
    float s = 0.f;
    #pragma unroll
    for (int j = 0; j < 16; j++) s += g_bufB[((size_t)b*16 + j)*512 + c];
    g_vec[i] = s * (1.f/16.f);
}

// ---------------------------------------------------------------------------
// FC layers
// ---------------------------------------------------------------------------
__global__ void fc_kernel(const float* __restrict__ W, const float* __restrict__ bias,
                          float* dout, int stage, int K, int O)
{
    const float* x = g_vec;
    if (stage == 1) x = g_fc1o;
    if (stage == 2) x = g_fc2o;
    float* y = g_fc1o;
    if (stage == 1) y = g_fc2o;
    if (stage == 2) y = dout;
    int relu = (stage < 2) ? 1 : 0;

    int o = blockIdx.x;
    float acc[8];
    #pragma unroll
    for (int i = 0; i < 8; i++) acc[i] = 0.f;
    const float* wr = W + (size_t)o * K;
    for (int k = threadIdx.x; k < K; k += 128) {
        float wv = wr[k];
        #pragma unroll
        for (int b = 0; b < 8; b++) acc[b] = fmaf(x[(size_t)b*K + k], wv, acc[b]);
    }
    __shared__ float red[8][128];
    #pragma unroll
    for (int b = 0; b < 8; b++) red[b][threadIdx.x] = acc[b];
    __syncthreads();
    for (int s = 64; s > 0; s >>= 1) {
        if (threadIdx.x < s) {
            #pragma unroll
            for (int b = 0; b < 8; b++)
                red[b][threadIdx.x] += red[b][threadIdx.x + s];
        }
        __syncthreads();
    }
    if (threadIdx.x < 8) {
        int b = threadIdx.x;
        float v = red[b][0] + bias[o];
        if (relu) v = fmaxf(v, 0.f);
        y[(size_t)b*O + o] = v;
    }
}

// ---------------------------------------------------------------------------
// Host orchestration
// ---------------------------------------------------------------------------
extern "C" void kernel_launch(void* const* d_in, const int* in_sizes, int n_in,
                              void* d_out, int out_size)
{
    const float* x = (const float*)d_in[0];
    const float* w[13];
    for (int i = 0; i < 13; i++) w[i] = (const float*)d_in[1+i];
    const float* fc1w = (const float*)d_in[14];
    const float* fc1b = (const float*)d_in[15];
    const float* fc2w = (const float*)d_in[16];
    const float* fc2b = (const float*)d_in[17];
    const float* fc3w = (const float*)d_in[18];
    const float* fc3b = (const float*)d_in[19];

    cudaFuncSetAttribute(gemm_kernel,
                         cudaFuncAttributeMaxDynamicSharedMemorySize, 61440);

    // launch 0: all sampling tables
    make_table_all<<<86, 256>>>();

    const int lC[13] = {3,64,64,128,128,256,256,256,512,512,512,512,512};
    const int lO[13] = {64,64,128,128,256,256,256,512,512,512,512,512,512};
    int kpad[13];
    int woff[13];
    int wacc = 0;
    int nblkA = 0, nblkB = 0;
    for (int i = 0; i < 13; i++) {
        kpad[i] = ((lC[i]*9 + 63) / 64) * 64;
        woff[i] = wacc;
        wacc += lO[i] * kpad[i];
        int nb = (lO[i]*kpad[i] + 255) / 256;
        if (i < 7) nblkA += nb; else nblkB += nb;
    }
    // launches 1,2: weight prep ranges (splits so ncu slot 5 = L12 sampler)
    wprep_range<<<nblkA, 256>>>(w[0],w[1],w[2],w[3],w[4],w[5],w[6],
                                w[7],w[8],w[9],w[10],w[11],w[12], 0, 7);
    wprep_range<<<nblkB, 256>>>(w[0],w[1],w[2],w[3],w[4],w[5],w[6],
                                w[7],w[8],w[9],w[10],w[11],w[12], 7, 13);

    const int tbase[5] = {0, 147456, 184320, 193536, 195840};
    const int lH[13]   = {128,128,64,64,32,32,32,16,16,16,8,8,8};
    const int lKS[13]  = {1,1,1,1,1,1,1,2,2,2,8,8,8};
    const int srcSel[13] = {0,1,1,2,2,1,2,2,1,2,2,1,2};
    const int dstSel[13] = {1,2,2,1,1,2,1,1,2,1,1,2,1};

    for (int li = 0; li < 13; li++) {
        int C = lC[li], O = lO[li], H = lH[li], kSplit = lKS[li];
        int HW = H * H;
        int Kpad = kpad[li];
        int ti = 4;
        if (HW == 16384) ti = 0;
        else if (HW == 4096) ti = 1;
        else if (HW == 1024) ti = 2;
        else if (HW == 256) ti = 3;

        int Npix = 8 * HW;
        if (li == 0) {
            sample_l11<<<(Npix + 255)/256, 256>>>(x);
        } else {
            int P = 256 / (C >> 3);
            sample_nhwc<<<Npix / P, 256>>>(srcSel[li], tbase[ti], C, HW, Kpad, Npix);
        }

        dim3 grid(Npix/128, O/64, kSplit);
        int outSel = dstSel[li];
        if (kSplit > 1) outSel = 3;
        gemm_kernel<<<grid, 256, 61440>>>(woff[li], outSel, O, Npix, Kpad, kSplit);
        if (kSplit > 1) {
            int n = O * Npix;
            reduce_relu_kernel<<<(n + 255)/256, 256>>>(dstSel[li], n, kSplit);
        }

        if (li == 1)  pool_kernel<<<(8*64*64*64  + 255)/256, 256>>>(2, 1, 64, 128);
        if (li == 3)  pool_kernel<<<(8*128*32*32 + 255)/256, 256>>>(1, 2, 128, 64);
        if (li == 6)  pool_kernel<<<(8*256*16*16 + 255)/256, 256>>>(1, 2, 256, 32);
        if (li == 9)  pool_kernel<<<(8*512*8*8   + 255)/256, 256>>>(1, 2, 512, 16);
        if (li == 12) pool_kernel<<<(8*512*4*4   + 255)/256, 256>>>(1, 2, 512, 8);
    }

    avg_kernel<<<(8*512 + 255)/256, 256>>>();

    fc_kernel<<<4096, 128>>>(fc1w, fc1b, (float*)d_out, 0, 512, 4096);
    fc_kernel<<<4096, 128>>>(fc2w, fc2b, (float*)d_out, 1, 4096, 4096);
    fc_kernel<<<30,   128>>>(fc3w, fc3b, (float*)d_out, 2, 4096, 30);
}